// round 5
// baseline (speedup 1.0000x reference)
#include <cuda_runtime.h>
#include <cstdint>

#define KC 512
#define DD 64
#define NB 32
#define HW 4096
#define NVEC (NB * HW)              // 131072 vectors
#define NTH 256
#define NPT 2
#define CHUNKN (NTH * NPT)          // 512 vectors per chunk
#define NCHUNK (NVEC / CHUNKN)      // 256 chunks
#define GRID 128
#define SMEM_BYTES (KC * DD * 4 + KC * 4 + 16)   // cb + cbsqr + maxbits

typedef unsigned long long u64;
typedef unsigned int u32;

__device__ __forceinline__ u64 ffma2(u64 a, u64 b, u64 c) {
    u64 d;
    asm("fma.rn.f32x2 %0, %1, %2, %3;" : "=l"(d) : "l"(a), "l"(b), "l"(c));
    return d;
}
__device__ __forceinline__ u64 pk(float lo, float hi) {
    u64 d;
    asm("mov.b64 %0, {%1, %2};" : "=l"(d) : "f"(lo), "f"(hi));
    return d;
}
__device__ __forceinline__ void unpack2(u64 a, float& lo, float& hi) {
    asm("mov.b64 {%0, %1}, %2;" : "=f"(lo), "=f"(hi) : "l"(a));
}

// Quarter-row FMA block: pairs 8q..8q+7; chain c consumes pairs == c (mod 4)
// in ascending order -- byte-identical accumulation order to rounds 1-3.
#define QFMA(bp, q)                                                         \
    do {                                                                    \
        u64 c0 = (bp)[0].x, c1 = (bp)[0].y, c2 = (bp)[1].x, c3 = (bp)[1].y; \
        a0 = ffma2(x2a[8*(q)+0], c0, a0); b0 = ffma2(x2b[8*(q)+0], c0, b0); \
        a1 = ffma2(x2a[8*(q)+1], c1, a1); b1 = ffma2(x2b[8*(q)+1], c1, b1); \
        a2 = ffma2(x2a[8*(q)+2], c2, a2); b2 = ffma2(x2b[8*(q)+2], c2, b2); \
        a3 = ffma2(x2a[8*(q)+3], c3, a3); b3 = ffma2(x2b[8*(q)+3], c3, b3); \
        u64 d0 = (bp)[2].x, d1 = (bp)[2].y, d2 = (bp)[3].x, d3 = (bp)[3].y; \
        a0 = ffma2(x2a[8*(q)+4], d0, a0); b0 = ffma2(x2b[8*(q)+4], d0, b0); \
        a1 = ffma2(x2a[8*(q)+5], d1, a1); b1 = ffma2(x2b[8*(q)+5], d1, b1); \
        a2 = ffma2(x2a[8*(q)+6], d2, a2); b2 = ffma2(x2b[8*(q)+6], d2, b2); \
        a3 = ffma2(x2a[8*(q)+7], d3, a3); b3 = ffma2(x2b[8*(q)+7], d3, b3); \
    } while (0)

// 4x LDS.128 prefetch of one quarter row.
#define PREF(bp, src)                                                       \
    do {                                                                    \
        (bp)[0] = (src)[0]; (bp)[1] = (src)[1];                             \
        (bp)[2] = (src)[2]; (bp)[3] = (src)[3];                             \
    } while (0)

// Scalar tree identical to round 3 (bit-exact; rel_err has been 0.0).
__device__ __forceinline__ float tree8(u64 a0, u64 a1, u64 a2, u64 a3) {
    float f0, f1, f2, f3, f4, f5, f6, f7;
    unpack2(a0, f0, f1); unpack2(a1, f2, f3);
    unpack2(a2, f4, f5); unpack2(a3, f6, f7);
    return ((f0 + f1) + (f2 + f3)) + ((f4 + f5) + (f6 + f7));
}

__global__ void __launch_bounds__(NTH, 1)
vq_kernel(const float* __restrict__ ze, const float* __restrict__ cbg,
          float* __restrict__ out, int write2) {
    extern __shared__ float sm[];
    float* cb      = sm;                        // [512][64]
    float* cbsqr   = sm + KC * DD;              // [512]
    int*   maxbits = (int*)(sm + KC * DD + KC); // max ||c||^2 bits
    const int tid = threadIdx.x;

    {
        const float4* g4 = (const float4*)cbg;
        float4*       s4 = (float4*)cb;
        #pragma unroll
        for (int i = tid; i < KC * DD / 4; i += NTH) s4[i] = g4[i];
        if (tid == 0) *maxbits = 0;
    }
    __syncthreads();
    for (int k = tid; k < KC; k += NTH) {
        const float* row = cb + k * DD;
        float s = 0.f;
        #pragma unroll
        for (int d = 0; d < DD; d++) s = fmaf(row[d], row[d], s);
        cbsqr[k] = s;
        atomicMax(maxbits, __float_as_int(s));  // s > 0 -> bits monotone
    }
    __syncthreads();
    const float cmax = sqrtf(__int_as_float(*maxbits));  // max ||c_k||

    const ulonglong2* c2p = (const ulonglong2*)cb;  // 16 per row

    for (int chunk = blockIdx.x; chunk < NCHUNK; chunk += gridDim.x) {
        const int n0 = chunk * CHUNKN + tid;
        const int b  = n0 >> 12;
        const int s0 = n0 & 4095;
        const float* xa = ze + (size_t)b * (DD * HW) + s0;
        const float* xb = xa + NTH;

        u64 x2a[DD / 2], x2b[DD / 2];
        float xsqra = 0.f, xsqrb = 0.f;
        #pragma unroll
        for (int j = 0; j < DD / 2; j++) {
            float la = xa[(size_t)(2 * j) * HW];
            float ha = xa[(size_t)(2 * j + 1) * HW];
            xsqra = fmaf(la, la, xsqra);
            xsqra = fmaf(ha, ha, xsqra);
            x2a[j] = pk(la, ha);
            float lb = xb[(size_t)(2 * j) * HW];
            float hb = xb[(size_t)(2 * j + 1) * HW];
            xsqrb = fmaf(lb, lb, xsqrb);
            xsqrb = fmaf(hb, hb, xsqrb);
            x2b[j] = pk(lb, hb);
        }

        // Per-vector lower bound: dist >= xsqr - 2||x||cmax (Cauchy-Schwarz),
        // minus 0.01 margin >> all rounding. dist > 0 -> bit-pattern order.
        float loa = fmaxf(xsqra - 2.f * sqrtf(xsqra) * cmax - 0.01f, 0.f);
        float lob = fmaxf(xsqrb - 2.f * sqrtf(xsqrb) * cmax - 0.01f, 0.f);
        const u32 Ba = (u32)__float_as_int(loa);
        const u32 Bb = (u32)__float_as_int(lob);

        u32 bestA = 0xFFFFFFFFu, bestB = 0xFFFFFFFFu;

        u64 a0 = 0, a1 = 0, a2 = 0, a3 = 0, b0 = 0, b1 = 0, b2 = 0, b3 = 0;
        u64 p0, p1, p2, p3, p4, p5, p6, p7;   // prev-k accumulators
        float ckm1;
        ulonglong2 B0[4], B1[4];
        PREF(B0, c2p);                         // row 0, quarter 0

        // ---- k = 0 peeled (no epilogue yet) ----
        {
            const ulonglong2* r = c2p;
            PREF(B1, r + 4);   QFMA(B0, 0);
            PREF(B0, r + 8);   QFMA(B1, 1);
            PREF(B1, r + 12);  QFMA(B0, 2);
            PREF(B0, r + 16);  QFMA(B1, 3);    // prefetch row 1 q0
            p0 = a0; p1 = a1; p2 = a2; p3 = a3;
            p4 = b0; p5 = b1; p6 = b2; p7 = b3;
            ckm1 = cbsqr[0];
            a0 = a1 = a2 = a3 = b0 = b1 = b2 = b3 = 0;
        }

        #pragma unroll 2
        for (int k = 1; k < KC; k++) {
            const ulonglong2* r = c2p + k * 16;
            PREF(B1, r + 4);   QFMA(B0, 0);
            // epilogue for vector a, row k-1 (overlaps row-k FMAs)
            {
                float dota = tree8(p0, p1, p2, p3);
                float da = fmaf(-2.0f, dota, ckm1 + xsqra);
                u32 key = (((u32)__float_as_int(da) - Ba) << 9) + (u32)(k - 1);
                bestA = min(bestA, key);
            }
            PREF(B0, r + 8);   QFMA(B1, 1);
            // epilogue for vector b, row k-1
            {
                float dotb = tree8(p4, p5, p6, p7);
                float db = fmaf(-2.0f, dotb, ckm1 + xsqrb);
                u32 key = (((u32)__float_as_int(db) - Bb) << 9) + (u32)(k - 1);
                bestB = min(bestB, key);
            }
            PREF(B1, r + 12);  QFMA(B0, 2);
            PREF(B0, r + 16);  QFMA(B1, 3);    // k=511 reads cbsqr area: in-bounds, unused
            p0 = a0; p1 = a1; p2 = a2; p3 = a3;
            p4 = b0; p5 = b1; p6 = b2; p7 = b3;
            ckm1 = cbsqr[k];
            a0 = a1 = a2 = a3 = b0 = b1 = b2 = b3 = 0;
        }
        // final epilogue, k = 511
        {
            float dota = tree8(p0, p1, p2, p3);
            float da = fmaf(-2.0f, dota, ckm1 + xsqra);
            u32 key = (((u32)__float_as_int(da) - Ba) << 9) + 511u;
            bestA = min(bestA, key);
            float dotb = tree8(p4, p5, p6, p7);
            float db = fmaf(-2.0f, dotb, ckm1 + xsqrb);
            u32 keyb = (((u32)__float_as_int(db) - Bb) << 9) + 511u;
            bestB = min(bestB, keyb);
        }
        const int bka = (int)(bestA & 511u);
        const int bkb = (int)(bestB & 511u);

        #pragma unroll
        for (int v = 0; v < NPT; v++) {
            const int   kk = (v == 0) ? bka : bkb;
            const int   ss = s0 + v * NTH;
            const float4* code4 = (const float4*)(cb + kk * DD);
            float* o1 = out + (size_t)b * (DD * HW) + ss;
            float* o2 = o1 + (size_t)NVEC * DD;
            #pragma unroll
            for (int q = 0; q < DD / 4; q++) {
                float4 w = code4[q];
                o1[(size_t)(4 * q + 0) * HW] = w.x;
                o1[(size_t)(4 * q + 1) * HW] = w.y;
                o1[(size_t)(4 * q + 2) * HW] = w.z;
                o1[(size_t)(4 * q + 3) * HW] = w.w;
                if (write2) {
                    o2[(size_t)(4 * q + 0) * HW] = w.x;
                    o2[(size_t)(4 * q + 1) * HW] = w.y;
                    o2[(size_t)(4 * q + 2) * HW] = w.z;
                    o2[(size_t)(4 * q + 3) * HW] = w.w;
                }
            }
        }
    }
}

extern "C" void kernel_launch(void* const* d_in, const int* in_sizes, int n_in,
                              void* d_out, int out_size) {
    const float* ze  = (const float*)d_in[0];   // z_e_x [32,64,64,64] f32
    const float* cbg = (const float*)d_in[1];   // codebook [512,64] f32
    float* out = (float*)d_out;
    const int write2 = (out_size >= 2 * NVEC * DD) ? 1 : 0;
    cudaFuncSetAttribute(vq_kernel, cudaFuncAttributeMaxDynamicSharedMemorySize,
                         (int)SMEM_BYTES);
    vq_kernel<<<GRID, NTH, SMEM_BYTES>>>(ze, cbg, out, write2);
}